// round 7
// baseline (speedup 1.0000x reference)
#include <cuda_runtime.h>
#include <cstdint>

#define N_MACRO       50000
#define D_FEAT        128
#define SEGS_PER_WARP 4
#define UNROLL        8

// lower_bound table: g_bounds[s] = first index i with seg_ids[i] >= s.
// Segment s spans [g_bounds[s], g_bounds[s+1]).
__device__ int g_bounds[N_MACRO + 1];

// ---------------------------------------------------------------------------
// Kernel 1: O(n) boundary detection, int4-vectorized (4 entries / thread).
// ---------------------------------------------------------------------------
__global__ void __launch_bounds__(256)
sp_bounds_kernel(const int* __restrict__ seg_ids, int n)
{
    int t  = blockIdx.x * blockDim.x + threadIdx.x;
    int i0 = t * 4;
    if (i0 >= n) return;

    int c0, c1, c2, c3;
    if (i0 + 3 < n) {
        int4 v = *reinterpret_cast<const int4*>(seg_ids + i0);
        c0 = v.x; c1 = v.y; c2 = v.z; c3 = v.w;
    } else {
        c0 = __ldg(&seg_ids[i0]);
        c1 = (i0 + 1 < n) ? __ldg(&seg_ids[i0 + 1]) : c0;
        c2 = (i0 + 2 < n) ? __ldg(&seg_ids[i0 + 2]) : c1;
        c3 = (i0 + 3 < n) ? __ldg(&seg_ids[i0 + 3]) : c2;
    }
    int prev = (i0 == 0) ? -1 : __ldg(&seg_ids[i0 - 1]);

    int cur[4] = {c0, c1, c2, c3};
    #pragma unroll
    for (int k = 0; k < 4; ++k) {
        int idx = i0 + k;
        if (idx < n) {
            for (int s = prev + 1; s <= cur[k]; ++s)
                g_bounds[s] = idx;
            prev = cur[k];
        }
    }
    if (i0 + 4 >= n) {               // last thread closes the table
        int last = prev;
        for (int s = last + 1; s <= N_MACRO; ++s)
            g_bounds[s] = n;
    }
}

// ---------------------------------------------------------------------------
// Kernel 2: gather + segment-mean.
// Warp owns 4 segments per grid-stride step; lane owns dims {2L,2L+1} and
// {64+2L,64+2L+1} => two LDG.64 per row (lower within-LDG replay cost than
// one LDG.128). 8-row batch => 16 independent loads in flight. Tail batch is
// predicated (clamped index, 0/1 weight) to keep MLP on short segments.
// ---------------------------------------------------------------------------
__global__ void __launch_bounds__(256, 2)
sp_pool_kernel(const float* __restrict__ feat,
               const int*   __restrict__ node_ids,
               float*       __restrict__ out)
{
    const int lane     = threadIdx.x & 31;
    const int warp0    = (blockIdx.x * blockDim.x + threadIdx.x) >> 5;
    const int n_warps  = (N_MACRO + SEGS_PER_WARP - 1) / SEGS_PER_WARP;
    const int wstride  = (gridDim.x * blockDim.x) >> 5;

    const int doff0 = lane * 2;        // dims 2L, 2L+1
    const int doff1 = 64 + lane * 2;   // dims 64+2L, 64+2L+1

    for (int warp = warp0; warp < n_warps; warp += wstride) {
        const int seg_base = warp * SEGS_PER_WARP;

        // lanes 0..4 fetch the 5 bounds for this warp's 4 segments
        int b = __ldg(&g_bounds[seg_base + min(lane, SEGS_PER_WARP)]);

        #pragma unroll
        for (int g = 0; g < SEGS_PER_WARP; ++g) {
            const int s0 = __shfl_sync(0xffffffffu, b, g);
            const int s1 = __shfl_sync(0xffffffffu, b, g + 1);
            const int cnt = s1 - s0;

            float4 acc = make_float4(0.f, 0.f, 0.f, 0.f);

            if (cnt > 0) {
                int j = s0;
                // full batches
                for (; j + UNROLL <= s1; j += UNROLL) {
                    int nid[UNROLL];
                    #pragma unroll
                    for (int k = 0; k < UNROLL; ++k)
                        nid[k] = __ldg(&node_ids[j + k]);
                    float2 va[UNROLL], vb[UNROLL];
                    #pragma unroll
                    for (int k = 0; k < UNROLL; ++k) {
                        const float* row = feat + (size_t)nid[k] * D_FEAT;
                        va[k] = *reinterpret_cast<const float2*>(row + doff0);
                        vb[k] = *reinterpret_cast<const float2*>(row + doff1);
                    }
                    #pragma unroll
                    for (int k = 0; k < UNROLL; ++k) {
                        acc.x += va[k].x; acc.y += va[k].y;
                        acc.z += vb[k].x; acc.w += vb[k].y;
                    }
                }
                // predicated tail batch (keeps loads independent)
                if (j < s1) {
                    int nid[UNROLL];
                    float w[UNROLL];
                    #pragma unroll
                    for (int k = 0; k < UNROLL; ++k) {
                        int jj = j + k;
                        int jc = (jj < s1) ? jj : (s1 - 1);
                        nid[k] = __ldg(&node_ids[jc]);
                        w[k]   = (jj < s1) ? 1.0f : 0.0f;
                    }
                    float2 va[UNROLL], vb[UNROLL];
                    #pragma unroll
                    for (int k = 0; k < UNROLL; ++k) {
                        const float* row = feat + (size_t)nid[k] * D_FEAT;
                        va[k] = *reinterpret_cast<const float2*>(row + doff0);
                        vb[k] = *reinterpret_cast<const float2*>(row + doff1);
                    }
                    #pragma unroll
                    for (int k = 0; k < UNROLL; ++k) {
                        acc.x = fmaf(va[k].x, w[k], acc.x);
                        acc.y = fmaf(va[k].y, w[k], acc.y);
                        acc.z = fmaf(vb[k].x, w[k], acc.z);
                        acc.w = fmaf(vb[k].y, w[k], acc.w);
                    }
                }
            }

            const float inv = (cnt > 0) ? (1.0f / (float)cnt) : 0.0f;
            float* o = out + (size_t)(seg_base + g) * D_FEAT;
            *reinterpret_cast<float2*>(o + doff0) =
                make_float2(acc.x * inv, acc.y * inv);
            *reinterpret_cast<float2*>(o + doff1) =
                make_float2(acc.z * inv, acc.w * inv);
        }
    }
}

// ---------------------------------------------------------------------------
// Launch
// inputs: node_feature f32 [100000*128], batch_node_ids i32 [n],
//         batch_macro_node_ids i32 [n] (sorted), num_macro_nodes (scalar)
// ---------------------------------------------------------------------------
extern "C" void kernel_launch(void* const* d_in, const int* in_sizes, int n_in,
                              void* d_out, int out_size) {
    const float* feat     = (const float*)d_in[0];
    const int*   node_ids = (const int*)d_in[1];
    const int*   seg_ids  = (const int*)d_in[2];
    float*       out      = (float*)d_out;
    const int n = in_sizes[1];

    if (n > 0) {
        int nt = (n + 3) / 4;
        sp_bounds_kernel<<<(nt + 255) / 256, 256>>>(seg_ids, n);
    }

    // persistent-ish grid: ~5 blocks/SM on 148 SMs, grid-stride over warps
    sp_pool_kernel<<<740, 256>>>(feat, node_ids, out);
}

// round 8
// speedup vs baseline: 1.0383x; 1.0383x over previous
#include <cuda_runtime.h>
#include <cstdint>

#define N_MACRO       50000
#define D_FEAT        128
#define SEGS_PER_WARP 4
#define UNROLL        8

// ---------------------------------------------------------------------------
// Single fused kernel: gather + segment-mean over sorted segment ids.
//   warp w -> segments [w*4, w*4+4)
//   lanes 0..4 binary-search lower_bound(seg_ids, base+lane) in parallel
//   lane owns 4 dims (one float4 = one LDG.128 per row)
//   8-row batch => 8 independent LDG.128 in flight (launch_bounds gives the
//   register budget so the batch stays live; 32-reg builds collapse it)
//   ragged tail handled as a predicated batch (clamped index, 0/1 weight)
// ---------------------------------------------------------------------------
__global__ void __launch_bounds__(256, 2)
sp_pool_kernel(const float* __restrict__ feat,
               const int*   __restrict__ node_ids,
               const int*   __restrict__ seg_ids,
               float*       __restrict__ out,
               int n)
{
    const int warp = (blockIdx.x * blockDim.x + threadIdx.x) >> 5;
    const int lane = threadIdx.x & 31;
    const int seg_base = warp * SEGS_PER_WARP;
    if (seg_base >= N_MACRO) return;

    // --- lanes 0..4 find lower_bound(seg_ids, seg_base + lane); all lanes
    // run the loop convergent (top of the search tree stays L1-resident).
    int target = seg_base + min(lane, SEGS_PER_WARP);
    int lo = 0, hi = n;
    while (lo < hi) {
        int mid = (lo + hi) >> 1;
        if (__ldg(&seg_ids[mid]) < target) lo = mid + 1;
        else                               hi = mid;
    }

    #pragma unroll
    for (int g = 0; g < SEGS_PER_WARP; ++g) {
        const int s0 = __shfl_sync(0xffffffffu, lo, g);
        const int s1 = __shfl_sync(0xffffffffu, lo, g + 1);
        const int cnt = s1 - s0;

        float4 acc = make_float4(0.f, 0.f, 0.f, 0.f);

        if (cnt > 0) {
            int j = s0;
            // full 8-row batches: 8 independent LDG.128
            for (; j + UNROLL <= s1; j += UNROLL) {
                int nid[UNROLL];
                #pragma unroll
                for (int k = 0; k < UNROLL; ++k)
                    nid[k] = __ldg(&node_ids[j + k]);
                float4 v[UNROLL];
                #pragma unroll
                for (int k = 0; k < UNROLL; ++k)
                    v[k] = *reinterpret_cast<const float4*>(
                        feat + (size_t)nid[k] * D_FEAT + lane * 4);
                #pragma unroll
                for (int k = 0; k < UNROLL; ++k) {
                    acc.x += v[k].x; acc.y += v[k].y;
                    acc.z += v[k].z; acc.w += v[k].w;
                }
            }
            // predicated tail batch (keeps loads independent)
            if (j < s1) {
                int   nid[UNROLL];
                float w[UNROLL];
                #pragma unroll
                for (int k = 0; k < UNROLL; ++k) {
                    int jj = j + k;
                    int jc = (jj < s1) ? jj : (s1 - 1);
                    nid[k] = __ldg(&node_ids[jc]);
                    w[k]   = (jj < s1) ? 1.0f : 0.0f;
                }
                float4 v[UNROLL];
                #pragma unroll
                for (int k = 0; k < UNROLL; ++k)
                    v[k] = *reinterpret_cast<const float4*>(
                        feat + (size_t)nid[k] * D_FEAT + lane * 4);
                #pragma unroll
                for (int k = 0; k < UNROLL; ++k) {
                    acc.x = fmaf(v[k].x, w[k], acc.x);
                    acc.y = fmaf(v[k].y, w[k], acc.y);
                    acc.z = fmaf(v[k].z, w[k], acc.z);
                    acc.w = fmaf(v[k].w, w[k], acc.w);
                }
            }
        }

        // mean (empty segment -> 0, matching sums / max(counts, 1))
        const float inv = (cnt > 0) ? (1.0f / (float)cnt) : 0.0f;
        float4 r = make_float4(acc.x * inv, acc.y * inv,
                               acc.z * inv, acc.w * inv);
        *reinterpret_cast<float4*>(
            out + (size_t)(seg_base + g) * D_FEAT + lane * 4) = r;
    }
}

// ---------------------------------------------------------------------------
// Launch
// inputs: node_feature f32 [100000*128], batch_node_ids i32 [n],
//         batch_macro_node_ids i32 [n] (sorted), num_macro_nodes (scalar)
// ---------------------------------------------------------------------------
extern "C" void kernel_launch(void* const* d_in, const int* in_sizes, int n_in,
                              void* d_out, int out_size) {
    const float* feat     = (const float*)d_in[0];
    const int*   node_ids = (const int*)d_in[1];
    const int*   seg_ids  = (const int*)d_in[2];
    float*       out      = (float*)d_out;
    const int n = in_sizes[1];

    const int n_warps  = (N_MACRO + SEGS_PER_WARP - 1) / SEGS_PER_WARP; // 12500
    const int n_blocks = (n_warps * 32 + 255) / 256;                    // 1563
    sp_pool_kernel<<<n_blocks, 256>>>(feat, node_ids, seg_ids, out, n);
}